// round 1
// baseline (speedup 1.0000x reference)
#include <cuda_runtime.h>
#include <cuda_bf16.h>
#include <math.h>

#define NN 100000
#define DD 128
#define EE 1600000
#define NB_SCAN 98   // ceil(NN/1024)
#define BN_EPS 1e-5f

// ---------------- device scratch (no runtime allocation allowed) ----------------
__device__ float g_bufA[NN * DD];
__device__ float g_bufB[NN * DD];
__device__ int   g_cnt[NN];          // histogram, then write cursor
__device__ int   g_rptr[NN + 1];
__device__ int   g_part[128];
__device__ int   g_part2[128];
__device__ int   g_cols[EE];
__device__ float g_wval[EE];
__device__ float g_sum[DD];
__device__ float g_sq[DD];
__device__ float g_scale[DD];
__device__ float g_shift[DD];

// ---------------- CSR build ----------------
__global__ void k_zero_cnt() {
    int i = blockIdx.x * blockDim.x + threadIdx.x;
    if (i < NN) g_cnt[i] = 0;
}

__global__ void k_count(const int* __restrict__ row) {
    int e = blockIdx.x * blockDim.x + threadIdx.x;
    if (e < EE) atomicAdd(&g_cnt[row[e]], 1);
}

__global__ __launch_bounds__(1024) void k_scan1() {
    __shared__ int s[1024];
    int t = threadIdx.x;
    int i = blockIdx.x * 1024 + t;
    int v = (i < NN) ? g_cnt[i] : 0;
    s[t] = v;
    #pragma unroll
    for (int off = 1; off < 1024; off <<= 1) {
        __syncthreads();
        int x = (t >= off) ? s[t - off] : 0;
        __syncthreads();
        s[t] += x;
    }
    int incl = s[t];
    if (i < NN) g_rptr[i] = incl - v;          // block-local exclusive
    if (t == 1023) g_part[blockIdx.x] = incl;  // block total
}

__global__ void k_scan2(int nb) {
    __shared__ int s[128];
    int t = threadIdx.x;
    int v = (t < nb) ? g_part[t] : 0;
    s[t] = v;
    #pragma unroll
    for (int off = 1; off < 128; off <<= 1) {
        __syncthreads();
        int x = (t >= off) ? s[t - off] : 0;
        __syncthreads();
        s[t] += x;
    }
    g_part2[t] = s[t] - v;  // exclusive
}

__global__ void k_scan3() {
    int i = blockIdx.x * blockDim.x + threadIdx.x;
    if (i < NN) {
        int v = g_rptr[i] + g_part2[i >> 10];
        g_rptr[i] = v;
        g_cnt[i] = v;   // write cursor
    }
    if (i == 0) g_rptr[NN] = EE;
}

__global__ void k_fill(const int* __restrict__ row, const int* __restrict__ col,
                       const float* __restrict__ ew) {
    int e = blockIdx.x * blockDim.x + threadIdx.x;
    if (e < EE) {
        int r = row[e];
        int p = atomicAdd(&g_cnt[r], 1);
        g_cols[p] = col[e];
        g_wval[p] = ew[e];
    }
}

// ---------------- GEMM: out[M,128] = act(A)[M,128] @ W[128,128] + b ----------------
// act(A) = useBN ? relu(scale[k]*A + shift[k]) : A   (applied on load, per column k)
// 128x128 block tile, 256 threads, 8x8 register tile, full-K resident in smem.
#define SMEM_GEMM (2 * 128 * 132 * 4)

__global__ __launch_bounds__(256, 1) void k_gemm(
    const float* __restrict__ A, const float* __restrict__ W,
    const float* __restrict__ bias, int useBN,
    float* __restrict__ out, int M)
{
    extern __shared__ float sm[];
    float* As = sm;               // [k][m]  : 128 x 132
    float* Ws = sm + 128 * 132;   // [k][n]  : 128 x 132
    int t = threadIdx.x;
    int m0 = blockIdx.x * 128;

    // load W (k-major already: W[k*128+n])
    #pragma unroll
    for (int p = 0; p < 16; p++) {
        int idx = p * 1024 + t * 4;
        int k = idx >> 7, n = idx & 127;
        float4 v = *(const float4*)(W + k * 128 + n);
        *(float4*)(Ws + k * 132 + n) = v;
    }
    // load A tile, apply optional BN+ReLU, transpose into k-major
    #pragma unroll
    for (int p = 0; p < 16; p++) {
        int idx = p * 1024 + t * 4;
        int r = idx >> 7, k = idx & 127;
        int gr = m0 + r;
        float4 v = make_float4(0.f, 0.f, 0.f, 0.f);
        if (gr < M) v = *(const float4*)(A + gr * 128 + k);
        if (useBN) {
            v.x = fmaxf(0.f, fmaf(v.x, g_scale[k + 0], g_shift[k + 0]));
            v.y = fmaxf(0.f, fmaf(v.y, g_scale[k + 1], g_shift[k + 1]));
            v.z = fmaxf(0.f, fmaf(v.z, g_scale[k + 2], g_shift[k + 2]));
            v.w = fmaxf(0.f, fmaf(v.w, g_scale[k + 3], g_shift[k + 3]));
        }
        As[(k + 0) * 132 + r] = v.x;
        As[(k + 1) * 132 + r] = v.y;
        As[(k + 2) * 132 + r] = v.z;
        As[(k + 3) * 132 + r] = v.w;
    }
    __syncthreads();

    int tx = t & 15, ty = t >> 4;
    int rb = ty * 8, cb = tx * 8;
    float acc[8][8];
    #pragma unroll
    for (int i = 0; i < 8; i++)
        #pragma unroll
        for (int j = 0; j < 8; j++) acc[i][j] = 0.f;

    #pragma unroll 8
    for (int k = 0; k < 128; k++) {
        float a[8], b[8];
        *(float4*)(a)     = *(float4*)(As + k * 132 + rb);
        *(float4*)(a + 4) = *(float4*)(As + k * 132 + rb + 4);
        *(float4*)(b)     = *(float4*)(Ws + k * 132 + cb);
        *(float4*)(b + 4) = *(float4*)(Ws + k * 132 + cb + 4);
        #pragma unroll
        for (int i = 0; i < 8; i++)
            #pragma unroll
            for (int j = 0; j < 8; j++)
                acc[i][j] = fmaf(a[i], b[j], acc[i][j]);
    }

    float bia[8];
    *(float4*)(bia)     = *(const float4*)(bias + cb);
    *(float4*)(bia + 4) = *(const float4*)(bias + cb + 4);
    #pragma unroll
    for (int i = 0; i < 8; i++) {
        int gr = m0 + rb + i;
        if (gr < M) {
            float4 o0 = make_float4(acc[i][0] + bia[0], acc[i][1] + bia[1],
                                    acc[i][2] + bia[2], acc[i][3] + bia[3]);
            float4 o1 = make_float4(acc[i][4] + bia[4], acc[i][5] + bia[5],
                                    acc[i][6] + bia[6], acc[i][7] + bia[7]);
            *(float4*)(out + gr * 128 + cb)     = o0;
            *(float4*)(out + gr * 128 + cb + 4) = o1;
        }
    }
}

// ---------------- SpMM gather: out[r] = sum_j w_j * h[col_j], one warp per row ----------------
__global__ __launch_bounds__(256) void k_spmm(const float4* __restrict__ h4,
                                              float4* __restrict__ out4)
{
    int warp = (blockIdx.x * blockDim.x + threadIdx.x) >> 5;
    int lane = threadIdx.x & 31;
    if (warp >= NN) return;
    int jb = g_rptr[warp], je = g_rptr[warp + 1];
    float4 acc = make_float4(0.f, 0.f, 0.f, 0.f);
    for (int j0 = jb; j0 < je; j0 += 32) {
        int myj = j0 + lane;
        int c = 0; float w = 0.f;
        if (myj < je) { c = g_cols[myj]; w = g_wval[myj]; }
        int cnt = min(32, je - j0);
        for (int i = 0; i < cnt; i++) {
            int cc   = __shfl_sync(0xffffffffu, c, i);
            float ww = __shfl_sync(0xffffffffu, w, i);
            float4 hv = h4[cc * 32 + lane];
            acc.x = fmaf(ww, hv.x, acc.x);
            acc.y = fmaf(ww, hv.y, acc.y);
            acc.z = fmaf(ww, hv.z, acc.z);
            acc.w = fmaf(ww, hv.w, acc.w);
        }
    }
    out4[warp * 32 + lane] = acc;
}

// ---------------- BN column stats ----------------
__global__ void k_zero_stats() {
    int t = threadIdx.x;
    if (t < DD) { g_sum[t] = 0.f; g_sq[t] = 0.f; }
}

__global__ __launch_bounds__(256) void k_colstats(const float4* __restrict__ h4) {
    __shared__ float ssum[DD];
    __shared__ float ssq[DD];
    int t = threadIdx.x;
    if (t < DD) { ssum[t] = 0.f; ssq[t] = 0.f; }
    __syncthreads();
    int lane = t & 31, w = t >> 5;
    float4 s = make_float4(0.f, 0.f, 0.f, 0.f);
    float4 q = make_float4(0.f, 0.f, 0.f, 0.f);
    for (int r = blockIdx.x * 8 + w; r < NN; r += gridDim.x * 8) {
        float4 v = h4[r * 32 + lane];
        s.x += v.x; s.y += v.y; s.z += v.z; s.w += v.w;
        q.x = fmaf(v.x, v.x, q.x); q.y = fmaf(v.y, v.y, q.y);
        q.z = fmaf(v.z, v.z, q.z); q.w = fmaf(v.w, v.w, q.w);
    }
    atomicAdd(&ssum[lane * 4 + 0], s.x);
    atomicAdd(&ssum[lane * 4 + 1], s.y);
    atomicAdd(&ssum[lane * 4 + 2], s.z);
    atomicAdd(&ssum[lane * 4 + 3], s.w);
    atomicAdd(&ssq[lane * 4 + 0], q.x);
    atomicAdd(&ssq[lane * 4 + 1], q.y);
    atomicAdd(&ssq[lane * 4 + 2], q.z);
    atomicAdd(&ssq[lane * 4 + 3], q.w);
    __syncthreads();
    if (t < DD) {
        atomicAdd(&g_sum[t], ssum[t]);
        atomicAdd(&g_sq[t], ssq[t]);
    }
}

__global__ void k_bnparams(const float* __restrict__ gamma, const float* __restrict__ beta) {
    int t = threadIdx.x;
    if (t >= DD) return;
    float invn = 1.0f / (float)NN;
    float m = g_sum[t] * invn;
    float v = g_sq[t] * invn - m * m;
    float sc = gamma[t] * rsqrtf(v + BN_EPS);
    g_scale[t] = sc;
    g_shift[t] = beta[t] - sc * m;
}

// ---------------- launch ----------------
extern "C" void kernel_launch(void* const* d_in, const int* in_sizes, int n_in,
                              void* d_out, int out_size) {
    (void)in_sizes; (void)n_in; (void)out_size;
    const float* x  = (const float*)d_in[0];
    const float* ew = (const float*)d_in[1];
    const float* W0 = (const float*)d_in[2];
    const float* b0 = (const float*)d_in[3];
    const float* g0 = (const float*)d_in[4];
    const float* be0= (const float*)d_in[5];
    const float* W1 = (const float*)d_in[6];
    const float* b1 = (const float*)d_in[7];
    const float* g1 = (const float*)d_in[8];
    const float* be1= (const float*)d_in[9];
    const float* W2 = (const float*)d_in[10];
    const float* b2 = (const float*)d_in[11];
    const int* row  = (const int*)d_in[12];
    const int* col  = (const int*)d_in[13];
    float* out = (float*)d_out;

    float *pA, *pB;
    cudaGetSymbolAddress((void**)&pA, g_bufA);
    cudaGetSymbolAddress((void**)&pB, g_bufB);

    cudaFuncSetAttribute(k_gemm, cudaFuncAttributeMaxDynamicSharedMemorySize, SMEM_GEMM);

    int gb256_N = (NN + 255) / 256;
    int gb256_E = (EE + 255) / 256;
    int gemm_blocks = (NN + 127) / 128;
    int spmm_blocks = (NN + 7) / 8;

    // CSR build
    k_zero_cnt<<<gb256_N, 256>>>();
    k_count<<<gb256_E, 256>>>(row);
    k_scan1<<<NB_SCAN, 1024>>>();
    k_scan2<<<1, 128>>>(NB_SCAN);
    k_scan3<<<gb256_N, 256>>>();
    k_fill<<<gb256_E, 256>>>(row, col, ew);

    // layer 0: linear -> spmm -> bn stats
    k_gemm<<<gemm_blocks, 256, SMEM_GEMM>>>(x, W0, b0, 0, pA, NN);
    k_spmm<<<spmm_blocks, 256>>>((const float4*)pA, (float4*)pB);
    k_zero_stats<<<1, 128>>>();
    k_colstats<<<256, 256>>>((const float4*)pB);
    k_bnparams<<<1, 128>>>(g0, be0);

    // layer 1: bnrelu(.)@W1+b1 -> spmm -> bn stats
    k_gemm<<<gemm_blocks, 256, SMEM_GEMM>>>(pB, W1, b1, 1, pA, NN);
    k_spmm<<<spmm_blocks, 256>>>((const float4*)pA, (float4*)pB);
    k_zero_stats<<<1, 128>>>();
    k_colstats<<<256, 256>>>((const float4*)pB);
    k_bnparams<<<1, 128>>>(g1, be1);

    // layer 2: bnrelu(.)@W2+b2 -> spmm -> out
    k_gemm<<<gemm_blocks, 256, SMEM_GEMM>>>(pB, W2, b2, 1, pA, NN);
    k_spmm<<<spmm_blocks, 256>>>((const float4*)pA, (float4*)out);
}

// round 3
// speedup vs baseline: 1.7574x; 1.7574x over previous
#include <cuda_runtime.h>
#include <cuda_fp16.h>
#include <math.h>
#include <stdint.h>

#define NN 100000
#define DD 128
#define EE 1600000
#define NB_SCAN 98
#define BN_EPS 1e-5f

// ---------------- helpers ----------------
__device__ __forceinline__ uint32_t smem_u32(const void* p) {
    uint32_t a;
    asm("{ .reg .u64 t; cvta.to.shared.u64 t, %1; cvt.u32.u64 %0, t; }" : "=r"(a) : "l"(p));
    return a;
}
__device__ __forceinline__ void ldsm4(uint32_t* r, uint32_t a) {
    asm volatile("ldmatrix.sync.aligned.m8n8.x4.shared.b16 {%0,%1,%2,%3}, [%4];"
        : "=r"(r[0]), "=r"(r[1]), "=r"(r[2]), "=r"(r[3]) : "r"(a));
}
__device__ __forceinline__ void ldsm4t(uint32_t* r, uint32_t a) {
    asm volatile("ldmatrix.sync.aligned.m8n8.x4.trans.shared.b16 {%0,%1,%2,%3}, [%4];"
        : "=r"(r[0]), "=r"(r[1]), "=r"(r[2]), "=r"(r[3]) : "r"(a));
}
__device__ __forceinline__ void mma_f16(float* c, const uint32_t* a, uint32_t b0, uint32_t b1) {
    asm volatile("mma.sync.aligned.m16n8k16.row.col.f32.f16.f16.f32 "
        "{%0,%1,%2,%3}, {%4,%5,%6,%7}, {%8,%9}, {%0,%1,%2,%3};"
        : "+f"(c[0]), "+f"(c[1]), "+f"(c[2]), "+f"(c[3])
        : "r"(a[0]), "r"(a[1]), "r"(a[2]), "r"(a[3]), "r"(b0), "r"(b1));
}

// ---------------- device scratch ----------------
__device__ float g_bufA[NN * DD];
__device__ float g_bufB[NN * DD];
__device__ int   g_cnt[NN];
__device__ int   g_rptr[NN + 1];
__device__ int   g_part[128];
__device__ int   g_part2[128];
__device__ int   g_cols[EE];
__device__ float g_wval[EE];
__device__ float g_sum[DD];
__device__ float g_sq[DD];
__device__ float g_scale[DD];
__device__ float g_shift[DD];
// W images: [layer][hi/lo][k:128][n:136 padded] fp16
__device__ __align__(16) __half g_wimg[3][2][128][136];

// ---------------- CSR build ----------------
__global__ void k_zero_cnt() {
    int i = blockIdx.x * blockDim.x + threadIdx.x;
    if (i < NN) g_cnt[i] = 0;
}
__global__ void k_count(const int* __restrict__ row) {
    int e = blockIdx.x * blockDim.x + threadIdx.x;
    if (e < EE) atomicAdd(&g_cnt[row[e]], 1);
}
__global__ __launch_bounds__(1024) void k_scan1() {
    __shared__ int s[1024];
    int t = threadIdx.x;
    int i = blockIdx.x * 1024 + t;
    int v = (i < NN) ? g_cnt[i] : 0;
    s[t] = v;
    #pragma unroll
    for (int off = 1; off < 1024; off <<= 1) {
        __syncthreads();
        int x = (t >= off) ? s[t - off] : 0;
        __syncthreads();
        s[t] += x;
    }
    int incl = s[t];
    if (i < NN) g_rptr[i] = incl - v;
    if (t == 1023) g_part[blockIdx.x] = incl;
}
__global__ void k_scan2(int nb) {
    __shared__ int s[128];
    int t = threadIdx.x;
    int v = (t < nb) ? g_part[t] : 0;
    s[t] = v;
    #pragma unroll
    for (int off = 1; off < 128; off <<= 1) {
        __syncthreads();
        int x = (t >= off) ? s[t - off] : 0;
        __syncthreads();
        s[t] += x;
    }
    g_part2[t] = s[t] - v;
}
__global__ void k_scan3() {
    int i = blockIdx.x * blockDim.x + threadIdx.x;
    if (i < NN) {
        int v = g_rptr[i] + g_part2[i >> 10];
        g_rptr[i] = v;
        g_cnt[i] = v;
    }
    if (i == 0) g_rptr[NN] = EE;
}
__global__ void k_fill(const int* __restrict__ row, const int* __restrict__ col,
                       const float* __restrict__ ew) {
    int e = blockIdx.x * blockDim.x + threadIdx.x;
    if (e < EE) {
        int r = row[e];
        int p = atomicAdd(&g_cnt[r], 1);
        g_cols[p] = col[e];
        g_wval[p] = ew[e];
    }
}

// ---------------- W prep: fp16 hi/lo split, [k][n] layout ----------------
// grid: 3*128 (layer, k), 128 threads (n)
__global__ void k_wprep(const float* __restrict__ W0, const float* __restrict__ W1,
                        const float* __restrict__ W2) {
    int l = blockIdx.x / 128;
    int k = blockIdx.x % 128;
    int n = threadIdx.x;
    const float* W = (l == 0) ? W0 : (l == 1) ? W1 : W2;
    float w = W[k * 128 + n];
    __half hi = __float2half_rn(w);
    __half lo = __float2half_rn(w - __half2float(hi));
    g_wimg[l][0][k][n] = hi;
    g_wimg[l][1][k][n] = lo;
}

// ---------------- tensor-core GEMM via mma.sync fp16x3 ----------------
// out[M,128] = act(A) @ W + b ; act = optional BN+ReLU per input column.
// Per CTA: 128-row tile, K split in 2 chunks of 64 (smem resident).
// smem: sAh[128][72], sAl[128][72] fp16 ; sWh[64][136], sWl[64][136] fp16
#define GEMM_SMEM (18432 * 2 + 17408 * 2)

__global__ __launch_bounds__(256) void k_gemm_tc(
    const float* __restrict__ A, int layer,
    const float* __restrict__ bias, int useBN,
    float* __restrict__ out, int M)
{
    extern __shared__ char sm[];
    __half* sAh = (__half*)sm;              // [128][72]
    __half* sAl = (__half*)(sm + 18432);
    int t = threadIdx.x, lane = t & 31, wid = t >> 5;
    int m0 = blockIdx.x * 128;
    int m_warp = (wid & 1) * 64;
    int n_warp = (wid >> 1) * 32;

    uint32_t sbase = smem_u32(sm);
    // ldmatrix per-lane base addresses
    uint32_t aAddrH = sbase + (uint32_t)(((m_warp + (lane & 15)) * 72 + (lane >> 4) * 8) * 2);
    uint32_t aAddrL = aAddrH + 18432;
    uint32_t wAddrH = sbase + 36864u + (uint32_t)(((lane & 15) * 136 + n_warp + (lane >> 4) * 8) * 2);
    uint32_t wAddrL = wAddrH + 17408;

    float acc[4][4][4] = {};

    for (int ch = 0; ch < 2; ch++) {
        // W chunk copy: 64 rows x 272B per split = 1088 float4
        const float4* whi = (const float4*)&g_wimg[layer][0][ch * 64][0];
        const float4* wlo = (const float4*)&g_wimg[layer][1][ch * 64][0];
        float4* dWh = (float4*)(sm + 36864);
        float4* dWl = (float4*)(sm + 54272);
        #pragma unroll
        for (int i = 0; i < 5; i++) {
            int idx = t + i * 256;
            if (idx < 1088) { dWh[idx] = whi[idx]; dWl[idx] = wlo[idx]; }
        }
        // A chunk: 128 rows x 64 cols fp32 = 2048 float4
        #pragma unroll
        for (int i = 0; i < 8; i++) {
            int idx = t + i * 256;
            int r = idx >> 4, kq = idx & 15;
            int gr = m0 + r;
            float4 v = make_float4(0.f, 0.f, 0.f, 0.f);
            if (gr < M) v = *(const float4*)(A + gr * 128 + ch * 64 + kq * 4);
            if (useBN) {
                int kg = ch * 64 + kq * 4;
                v.x = fmaxf(0.f, fmaf(v.x, g_scale[kg + 0], g_shift[kg + 0]));
                v.y = fmaxf(0.f, fmaf(v.y, g_scale[kg + 1], g_shift[kg + 1]));
                v.z = fmaxf(0.f, fmaf(v.z, g_scale[kg + 2], g_shift[kg + 2]));
                v.w = fmaxf(0.f, fmaf(v.w, g_scale[kg + 3], g_shift[kg + 3]));
            }
            __half hx = __float2half_rn(v.x), hy = __float2half_rn(v.y);
            __half hz = __float2half_rn(v.z), hw = __float2half_rn(v.w);
            __half2 h01 = __halves2half2(hx, hy), h23 = __halves2half2(hz, hw);
            __half2 l01 = __floats2half2_rn(v.x - __half2float(hx), v.y - __half2float(hy));
            __half2 l23 = __floats2half2_rn(v.z - __half2float(hz), v.w - __half2float(hw));
            uint2 uh, ul;
            uh.x = *(uint32_t*)&h01; uh.y = *(uint32_t*)&h23;
            ul.x = *(uint32_t*)&l01; ul.y = *(uint32_t*)&l23;
            *(uint2*)&sAh[r * 72 + kq * 4] = uh;
            *(uint2*)&sAl[r * 72 + kq * 4] = ul;
        }
        __syncthreads();

        #pragma unroll
        for (int ks = 0; ks < 4; ks++) {
            int k0 = ks * 16;
            uint32_t Ah[4][4], Al[4][4], Wh[2][4], Wl[2][4];
            #pragma unroll
            for (int mt = 0; mt < 4; mt++) {
                uint32_t off = (uint32_t)((mt * 16 * 72 + k0) * 2);
                ldsm4(Ah[mt], aAddrH + off);
                ldsm4(Al[mt], aAddrL + off);
            }
            #pragma unroll
            for (int ng = 0; ng < 2; ng++) {
                uint32_t off = (uint32_t)((k0 * 136 + ng * 16) * 2);
                ldsm4t(Wh[ng], wAddrH + off);
                ldsm4t(Wl[ng], wAddrL + off);
            }
            #pragma unroll
            for (int mt = 0; mt < 4; mt++)
                #pragma unroll
                for (int nt = 0; nt < 4; nt++) {
                    int ng = nt >> 1, s = (nt & 1) * 2;
                    mma_f16(acc[mt][nt], Ah[mt], Wh[ng][s], Wh[ng][s + 1]);
                    mma_f16(acc[mt][nt], Ah[mt], Wl[ng][s], Wl[ng][s + 1]);
                    mma_f16(acc[mt][nt], Al[mt], Wh[ng][s], Wh[ng][s + 1]);
                }
        }
        __syncthreads();
    }

    // epilogue + bias
    #pragma unroll
    for (int mt = 0; mt < 4; mt++) {
        int r0 = m0 + m_warp + mt * 16 + (lane >> 2);
        #pragma unroll
        for (int nt = 0; nt < 4; nt++) {
            int col = n_warp + nt * 8 + (lane & 3) * 2;
            float b0 = bias[col], b1 = bias[col + 1];
            if (r0 < M) {
                float2 o = make_float2(acc[mt][nt][0] + b0, acc[mt][nt][1] + b1);
                *(float2*)(out + r0 * 128 + col) = o;
            }
            if (r0 + 8 < M) {
                float2 o = make_float2(acc[mt][nt][2] + b0, acc[mt][nt][3] + b1);
                *(float2*)(out + (r0 + 8) * 128 + col) = o;
            }
        }
    }
}

// ---------------- SpMM gather + fused BN stats ----------------
__global__ __launch_bounds__(256) void k_spmm2(const float4* __restrict__ h4,
                                               float4* __restrict__ out4, int doStats)
{
    __shared__ float ssum[DD];
    __shared__ float ssq[DD];
    int t = threadIdx.x;
    if (doStats) {
        if (t < DD) { ssum[t] = 0.f; ssq[t] = 0.f; }
        __syncthreads();
    }
    int lane = t & 31;
    int gw = (blockIdx.x * 256 + t) >> 5;
    int nw = (gridDim.x * 256) >> 5;

    float4 as = make_float4(0.f, 0.f, 0.f, 0.f);
    float4 aq = make_float4(0.f, 0.f, 0.f, 0.f);

    for (int r = gw; r < NN; r += nw) {
        int jb = g_rptr[r], je = g_rptr[r + 1];
        float4 acc = make_float4(0.f, 0.f, 0.f, 0.f);
        for (int j0 = jb; j0 < je; j0 += 32) {
            int myj = j0 + lane;
            int c = 0; float w = 0.f;
            if (myj < je) { c = g_cols[myj]; w = g_wval[myj]; }
            int cnt = min(32, je - j0);
            for (int i = 0; i < cnt; i++) {
                int cc   = __shfl_sync(0xffffffffu, c, i);
                float ww = __shfl_sync(0xffffffffu, w, i);
                float4 hv = h4[cc * 32 + lane];
                acc.x = fmaf(ww, hv.x, acc.x);
                acc.y = fmaf(ww, hv.y, acc.y);
                acc.z = fmaf(ww, hv.z, acc.z);
                acc.w = fmaf(ww, hv.w, acc.w);
            }
        }
        out4[r * 32 + lane] = acc;
        if (doStats) {
            as.x += acc.x; as.y += acc.y; as.z += acc.z; as.w += acc.w;
            aq.x = fmaf(acc.x, acc.x, aq.x); aq.y = fmaf(acc.y, acc.y, aq.y);
            aq.z = fmaf(acc.z, acc.z, aq.z); aq.w = fmaf(acc.w, acc.w, aq.w);
        }
    }
    if (doStats) {
        atomicAdd(&ssum[lane * 4 + 0], as.x);
        atomicAdd(&ssum[lane * 4 + 1], as.y);
        atomicAdd(&ssum[lane * 4 + 2], as.z);
        atomicAdd(&ssum[lane * 4 + 3], as.w);
        atomicAdd(&ssq[lane * 4 + 0], aq.x);
        atomicAdd(&ssq[lane * 4 + 1], aq.y);
        atomicAdd(&ssq[lane * 4 + 2], aq.z);
        atomicAdd(&ssq[lane * 4 + 3], aq.w);
        __syncthreads();
        if (t < DD) {
            atomicAdd(&g_sum[t], ssum[t]);
            atomicAdd(&g_sq[t], ssq[t]);
        }
    }
}

// ---------------- BN ----------------
__global__ void k_zero_stats() {
    int t = threadIdx.x;
    if (t < DD) { g_sum[t] = 0.f; g_sq[t] = 0.f; }
}
__global__ void k_bnparams(const float* __restrict__ gamma, const float* __restrict__ beta) {
    int t = threadIdx.x;
    if (t >= DD) return;
    float invn = 1.0f / (float)NN;
    float m = g_sum[t] * invn;
    float v = g_sq[t] * invn - m * m;
    float sc = gamma[t] * rsqrtf(v + BN_EPS);
    g_scale[t] = sc;
    g_shift[t] = beta[t] - sc * m;
}

// ---------------- launch ----------------
extern "C" void kernel_launch(void* const* d_in, const int* in_sizes, int n_in,
                              void* d_out, int out_size) {
    (void)in_sizes; (void)n_in; (void)out_size;
    const float* x  = (const float*)d_in[0];
    const float* ew = (const float*)d_in[1];
    const float* W0 = (const float*)d_in[2];
    const float* b0 = (const float*)d_in[3];
    const float* g0 = (const float*)d_in[4];
    const float* be0= (const float*)d_in[5];
    const float* W1 = (const float*)d_in[6];
    const float* b1 = (const float*)d_in[7];
    const float* g1 = (const float*)d_in[8];
    const float* be1= (const float*)d_in[9];
    const float* W2 = (const float*)d_in[10];
    const float* b2 = (const float*)d_in[11];
    const int* row  = (const int*)d_in[12];
    const int* col  = (const int*)d_in[13];
    float* out = (float*)d_out;

    float *pA, *pB;
    cudaGetSymbolAddress((void**)&pA, g_bufA);
    cudaGetSymbolAddress((void**)&pB, g_bufB);

    static cudaStream_t s_csr = nullptr;
    static cudaEvent_t e_fork = nullptr, e_join = nullptr;
    if (s_csr == nullptr) {
        cudaStreamCreateWithFlags(&s_csr, cudaStreamNonBlocking);
        cudaEventCreateWithFlags(&e_fork, cudaEventDisableTiming);
        cudaEventCreateWithFlags(&e_join, cudaEventDisableTiming);
        cudaFuncSetAttribute(k_gemm_tc, cudaFuncAttributeMaxDynamicSharedMemorySize, GEMM_SMEM);
    }

    int gb256_N = (NN + 255) / 256;
    int gb256_E = (EE + 255) / 256;
    int gemm_blocks = (NN + 127) / 128;
    int spmm_blocks = 1184;

    // fork: CSR build runs concurrently with W prep + layer-0 GEMM
    cudaEventRecord(e_fork, 0);
    cudaStreamWaitEvent(s_csr, e_fork, 0);
    k_zero_cnt<<<gb256_N, 256, 0, s_csr>>>();
    k_count<<<gb256_E, 256, 0, s_csr>>>(row);
    k_scan1<<<NB_SCAN, 1024, 0, s_csr>>>();
    k_scan2<<<1, 128, 0, s_csr>>>(NB_SCAN);
    k_scan3<<<gb256_N, 256, 0, s_csr>>>();
    k_fill<<<gb256_E, 256, 0, s_csr>>>(row, col, ew);
    cudaEventRecord(e_join, s_csr);

    // main stream: layer 0 GEMM
    k_wprep<<<3 * 128, 128>>>(W0, W1, W2);
    k_zero_stats<<<1, 128>>>();
    k_gemm_tc<<<gemm_blocks, 256, GEMM_SMEM>>>(x, 0, b0, 0, pA, NN);

    // join CSR before SpMM
    cudaStreamWaitEvent(0, e_join, 0);

    k_spmm2<<<spmm_blocks, 256>>>((const float4*)pA, (float4*)pB, 1);
    k_bnparams<<<1, 128>>>(g0, be0);

    // layer 1
    k_zero_stats<<<1, 128>>>();
    k_gemm_tc<<<gemm_blocks, 256, GEMM_SMEM>>>(pB, 1, b1, 1, pA, NN);
    k_spmm2<<<spmm_blocks, 256>>>((const float4*)pA, (float4*)pB, 1);
    k_bnparams<<<1, 128>>>(g1, be1);

    // layer 2 (no stats)
    k_gemm_tc<<<gemm_blocks, 256, GEMM_SMEM>>>(pB, 2, b2, 1, pA, NN);
    k_spmm2<<<spmm_blocks, 256>>>((const float4*)pA, (float4*)out, 0);
}

// round 4
// speedup vs baseline: 1.8251x; 1.0385x over previous
#include <cuda_runtime.h>
#include <cuda_fp16.h>
#include <math.h>
#include <stdint.h>

#define NN 100000
#define DD 128
#define EE 1600000
#define NB_SCAN 98
#define BN_EPS 1e-5f

// ---------------- helpers ----------------
__device__ __forceinline__ uint32_t smem_u32(const void* p) {
    uint32_t a;
    asm("{ .reg .u64 t; cvta.to.shared.u64 t, %1; cvt.u32.u64 %0, t; }" : "=r"(a) : "l"(p));
    return a;
}
__device__ __forceinline__ void ldsm4(uint32_t* r, uint32_t a) {
    asm volatile("ldmatrix.sync.aligned.m8n8.x4.shared.b16 {%0,%1,%2,%3}, [%4];"
        : "=r"(r[0]), "=r"(r[1]), "=r"(r[2]), "=r"(r[3]) : "r"(a));
}
__device__ __forceinline__ void ldsm4t(uint32_t* r, uint32_t a) {
    asm volatile("ldmatrix.sync.aligned.m8n8.x4.trans.shared.b16 {%0,%1,%2,%3}, [%4];"
        : "=r"(r[0]), "=r"(r[1]), "=r"(r[2]), "=r"(r[3]) : "r"(a));
}
__device__ __forceinline__ void mma_f16(float* c, const uint32_t* a, uint32_t b0, uint32_t b1) {
    asm volatile("mma.sync.aligned.m16n8k16.row.col.f32.f16.f16.f32 "
        "{%0,%1,%2,%3}, {%4,%5,%6,%7}, {%8,%9}, {%0,%1,%2,%3};"
        : "+f"(c[0]), "+f"(c[1]), "+f"(c[2]), "+f"(c[3])
        : "r"(a[0]), "r"(a[1]), "r"(a[2]), "r"(a[3]), "r"(b0), "r"(b1));
}

// ---------------- device scratch ----------------
__device__ float  g_bufA[NN * DD];                 // fp32 spmm output / gemm input
__device__ __align__(16) __half g_h16[NN * DD];    // fp16 gemm output / spmm gather source
__device__ int   g_cnt[NN];
__device__ int   g_rptr[NN + 1];
__device__ int   g_part[128];
__device__ int   g_part2[128];
__device__ int   g_cols[EE];
__device__ float g_wval[EE];
__device__ float g_sum[2][DD];
__device__ float g_sq[2][DD];
__device__ float g_scale[DD];
__device__ float g_shift[DD];
// W images: [layer][hi/lo][k:128][n:136 padded] fp16
__device__ __align__(16) __half g_wimg[3][2][128][136];

// ---------------- CSR build ----------------
__global__ void k_zero_cnt() {
    int i = blockIdx.x * blockDim.x + threadIdx.x;
    if (i < NN) g_cnt[i] = 0;
    if (i < 2 * DD) { (&g_sum[0][0])[i] = 0.f; (&g_sq[0][0])[i] = 0.f; }
}
__global__ void k_count(const int* __restrict__ row) {
    int e = blockIdx.x * blockDim.x + threadIdx.x;
    if (e < EE) atomicAdd(&g_cnt[row[e]], 1);
}
__global__ __launch_bounds__(1024) void k_scan1() {
    __shared__ int s[1024];
    int t = threadIdx.x;
    int i = blockIdx.x * 1024 + t;
    int v = (i < NN) ? g_cnt[i] : 0;
    s[t] = v;
    #pragma unroll
    for (int off = 1; off < 1024; off <<= 1) {
        __syncthreads();
        int x = (t >= off) ? s[t - off] : 0;
        __syncthreads();
        s[t] += x;
    }
    int incl = s[t];
    if (i < NN) g_rptr[i] = incl - v;
    if (t == 1023) g_part[blockIdx.x] = incl;
}
__global__ void k_scan2(int nb) {
    __shared__ int s[128];
    int t = threadIdx.x;
    int v = (t < nb) ? g_part[t] : 0;
    s[t] = v;
    #pragma unroll
    for (int off = 1; off < 128; off <<= 1) {
        __syncthreads();
        int x = (t >= off) ? s[t - off] : 0;
        __syncthreads();
        s[t] += x;
    }
    g_part2[t] = s[t] - v;
}
__global__ void k_scan3() {
    int i = blockIdx.x * blockDim.x + threadIdx.x;
    if (i < NN) {
        int v = g_rptr[i] + g_part2[i >> 10];
        g_rptr[i] = v;
        g_cnt[i] = v;
    }
    if (i == 0) g_rptr[NN] = EE;
}
__global__ void k_fill(const int* __restrict__ row, const int* __restrict__ col,
                       const float* __restrict__ ew) {
    int e = blockIdx.x * blockDim.x + threadIdx.x;
    if (e < EE) {
        int r = row[e];
        int p = atomicAdd(&g_cnt[r], 1);
        g_cols[p] = col[e];
        g_wval[p] = ew[e];
    }
}

// ---------------- W prep: fp16 hi/lo split, [k][n] layout ----------------
__global__ void k_wprep(const float* __restrict__ W0, const float* __restrict__ W1,
                        const float* __restrict__ W2) {
    int l = blockIdx.x / 128;
    int k = blockIdx.x % 128;
    int n = threadIdx.x;
    const float* W = (l == 0) ? W0 : (l == 1) ? W1 : W2;
    float w = W[k * 128 + n];
    __half hi = __float2half_rn(w);
    __half lo = __float2half_rn(w - __half2float(hi));
    g_wimg[l][0][k][n] = hi;
    g_wimg[l][1][k][n] = lo;
}

// ---------------- tensor-core GEMM via mma.sync fp16x3, fp16 output ----------------
#define GEMM_SMEM (18432 * 2 + 17408 * 2)

__global__ __launch_bounds__(256) void k_gemm_tc(
    const float* __restrict__ A, int layer,
    const float* __restrict__ bias, int useBN,
    __half* __restrict__ out16, int M)
{
    extern __shared__ char sm[];
    __half* sAh = (__half*)sm;              // [128][72]
    __half* sAl = (__half*)(sm + 18432);
    int t = threadIdx.x, lane = t & 31, wid = t >> 5;
    int m0 = blockIdx.x * 128;
    int m_warp = (wid & 1) * 64;
    int n_warp = (wid >> 1) * 32;

    uint32_t sbase = smem_u32(sm);
    uint32_t aAddrH = sbase + (uint32_t)(((m_warp + (lane & 15)) * 72 + (lane >> 4) * 8) * 2);
    uint32_t aAddrL = aAddrH + 18432;
    uint32_t wAddrH = sbase + 36864u + (uint32_t)(((lane & 15) * 136 + n_warp + (lane >> 4) * 8) * 2);
    uint32_t wAddrL = wAddrH + 17408;

    float acc[4][4][4] = {};

    for (int ch = 0; ch < 2; ch++) {
        const float4* whi = (const float4*)&g_wimg[layer][0][ch * 64][0];
        const float4* wlo = (const float4*)&g_wimg[layer][1][ch * 64][0];
        float4* dWh = (float4*)(sm + 36864);
        float4* dWl = (float4*)(sm + 54272);
        #pragma unroll
        for (int i = 0; i < 5; i++) {
            int idx = t + i * 256;
            if (idx < 1088) { dWh[idx] = whi[idx]; dWl[idx] = wlo[idx]; }
        }
        #pragma unroll
        for (int i = 0; i < 8; i++) {
            int idx = t + i * 256;
            int r = idx >> 4, kq = idx & 15;
            int gr = m0 + r;
            float4 v = make_float4(0.f, 0.f, 0.f, 0.f);
            if (gr < M) v = *(const float4*)(A + gr * 128 + ch * 64 + kq * 4);
            if (useBN) {
                int kg = ch * 64 + kq * 4;
                v.x = fmaxf(0.f, fmaf(v.x, g_scale[kg + 0], g_shift[kg + 0]));
                v.y = fmaxf(0.f, fmaf(v.y, g_scale[kg + 1], g_shift[kg + 1]));
                v.z = fmaxf(0.f, fmaf(v.z, g_scale[kg + 2], g_shift[kg + 2]));
                v.w = fmaxf(0.f, fmaf(v.w, g_scale[kg + 3], g_shift[kg + 3]));
            }
            __half hx = __float2half_rn(v.x), hy = __float2half_rn(v.y);
            __half hz = __float2half_rn(v.z), hw = __float2half_rn(v.w);
            __half2 h01 = __halves2half2(hx, hy), h23 = __halves2half2(hz, hw);
            __half2 l01 = __floats2half2_rn(v.x - __half2float(hx), v.y - __half2float(hy));
            __half2 l23 = __floats2half2_rn(v.z - __half2float(hz), v.w - __half2float(hw));
            uint2 uh, ul;
            uh.x = *(uint32_t*)&h01; uh.y = *(uint32_t*)&h23;
            ul.x = *(uint32_t*)&l01; ul.y = *(uint32_t*)&l23;
            *(uint2*)&sAh[r * 72 + kq * 4] = uh;
            *(uint2*)&sAl[r * 72 + kq * 4] = ul;
        }
        __syncthreads();

        #pragma unroll
        for (int ks = 0; ks < 4; ks++) {
            int k0 = ks * 16;
            uint32_t Ah[4][4], Al[4][4], Wh[2][4], Wl[2][4];
            #pragma unroll
            for (int mt = 0; mt < 4; mt++) {
                uint32_t off = (uint32_t)((mt * 16 * 72 + k0) * 2);
                ldsm4(Ah[mt], aAddrH + off);
                ldsm4(Al[mt], aAddrL + off);
            }
            #pragma unroll
            for (int ng = 0; ng < 2; ng++) {
                uint32_t off = (uint32_t)((k0 * 136 + ng * 16) * 2);
                ldsm4t(Wh[ng], wAddrH + off);
                ldsm4t(Wl[ng], wAddrL + off);
            }
            #pragma unroll
            for (int mt = 0; mt < 4; mt++)
                #pragma unroll
                for (int nt = 0; nt < 4; nt++) {
                    int ng = nt >> 1, s = (nt & 1) * 2;
                    mma_f16(acc[mt][nt], Ah[mt], Wh[ng][s], Wh[ng][s + 1]);
                    mma_f16(acc[mt][nt], Ah[mt], Wl[ng][s], Wl[ng][s + 1]);
                    mma_f16(acc[mt][nt], Al[mt], Wh[ng][s], Wh[ng][s + 1]);
                }
        }
        __syncthreads();
    }

    // epilogue + bias, fp16 store
    #pragma unroll
    for (int mt = 0; mt < 4; mt++) {
        int r0 = m0 + m_warp + mt * 16 + (lane >> 2);
        #pragma unroll
        for (int nt = 0; nt < 4; nt++) {
            int col = n_warp + nt * 8 + (lane & 3) * 2;
            float b0 = bias[col], b1 = bias[col + 1];
            if (r0 < M) {
                __half2 o = __floats2half2_rn(acc[mt][nt][0] + b0, acc[mt][nt][1] + b1);
                *(__half2*)(out16 + r0 * 128 + col) = o;
            }
            if (r0 + 8 < M) {
                __half2 o = __floats2half2_rn(acc[mt][nt][2] + b0, acc[mt][nt][3] + b1);
                *(__half2*)(out16 + (r0 + 8) * 128 + col) = o;
            }
        }
    }
}

// ---------------- SpMM gather (fp16 rows) + fused BN stats ----------------
// 16 lanes per neighbor, 2 neighbors per warp-iter via half-warps, fp32 accum.
__global__ __launch_bounds__(256) void k_spmm3(const uint4* __restrict__ h16,
                                               float4* __restrict__ out4, int statSlot)
{
    __shared__ float ssum[DD];
    __shared__ float ssq[DD];
    int t = threadIdx.x;
    if (statSlot >= 0) {
        if (t < DD) { ssum[t] = 0.f; ssq[t] = 0.f; }
        __syncthreads();
    }
    int lane = t & 31;
    int hw = lane >> 4;       // half-warp id
    int sl = lane & 15;       // slot in half-warp; covers cols 8*sl..8*sl+7
    int gw = (blockIdx.x * 256 + t) >> 5;
    int nw = (gridDim.x * 256) >> 5;

    float as[8] = {}, aq[8] = {};

    for (int r = gw; r < NN; r += nw) {
        int jb = g_rptr[r], je = g_rptr[r + 1];
        float acc[8] = {};
        for (int j0 = jb; j0 < je; j0 += 32) {
            int myj = j0 + lane;
            int c = 0; float w = 0.f;
            if (myj < je) { c = g_cols[myj]; w = g_wval[myj]; }
            int cnt = min(32, je - j0);
            for (int i = 0; i < cnt; i += 2) {
                int idx = i + hw;
                int cc   = __shfl_sync(0xffffffffu, c, idx);
                float ww = __shfl_sync(0xffffffffu, w, idx);
                if (idx < cnt) {
                    uint4 hv = h16[cc * 16 + sl];
                    float2 f0 = __half22float2(*(__half2*)&hv.x);
                    float2 f1 = __half22float2(*(__half2*)&hv.y);
                    float2 f2 = __half22float2(*(__half2*)&hv.z);
                    float2 f3 = __half22float2(*(__half2*)&hv.w);
                    acc[0] = fmaf(ww, f0.x, acc[0]);
                    acc[1] = fmaf(ww, f0.y, acc[1]);
                    acc[2] = fmaf(ww, f1.x, acc[2]);
                    acc[3] = fmaf(ww, f1.y, acc[3]);
                    acc[4] = fmaf(ww, f2.x, acc[4]);
                    acc[5] = fmaf(ww, f2.y, acc[5]);
                    acc[6] = fmaf(ww, f3.x, acc[6]);
                    acc[7] = fmaf(ww, f3.y, acc[7]);
                }
            }
        }
        // combine half-warps
        #pragma unroll
        for (int k = 0; k < 8; k++)
            acc[k] += __shfl_xor_sync(0xffffffffu, acc[k], 16);
        if (lane < 16) {
            float4 o0 = make_float4(acc[0], acc[1], acc[2], acc[3]);
            float4 o1 = make_float4(acc[4], acc[5], acc[6], acc[7]);
            out4[r * 32 + sl * 2 + 0] = o0;
            out4[r * 32 + sl * 2 + 1] = o1;
            if (statSlot >= 0) {
                #pragma unroll
                for (int k = 0; k < 8; k++) {
                    as[k] += acc[k];
                    aq[k] = fmaf(acc[k], acc[k], aq[k]);
                }
            }
        }
    }
    if (statSlot >= 0) {
        if (lane < 16) {
            #pragma unroll
            for (int k = 0; k < 8; k++) {
                atomicAdd(&ssum[sl * 8 + k], as[k]);
                atomicAdd(&ssq[sl * 8 + k], aq[k]);
            }
        }
        __syncthreads();
        if (t < DD) {
            atomicAdd(&g_sum[statSlot][t], ssum[t]);
            atomicAdd(&g_sq[statSlot][t], ssq[t]);
        }
    }
}

// ---------------- BN params ----------------
__global__ void k_bnparams(const float* __restrict__ gamma, const float* __restrict__ beta,
                           int slot) {
    int t = threadIdx.x;
    if (t >= DD) return;
    float invn = 1.0f / (float)NN;
    float m = g_sum[slot][t] * invn;
    float v = g_sq[slot][t] * invn - m * m;
    float sc = gamma[t] * rsqrtf(v + BN_EPS);
    g_scale[t] = sc;
    g_shift[t] = beta[t] - sc * m;
}

// ---------------- launch ----------------
extern "C" void kernel_launch(void* const* d_in, const int* in_sizes, int n_in,
                              void* d_out, int out_size) {
    (void)in_sizes; (void)n_in; (void)out_size;
    const float* x  = (const float*)d_in[0];
    const float* ew = (const float*)d_in[1];
    const float* W0 = (const float*)d_in[2];
    const float* b0 = (const float*)d_in[3];
    const float* g0 = (const float*)d_in[4];
    const float* be0= (const float*)d_in[5];
    const float* W1 = (const float*)d_in[6];
    const float* b1 = (const float*)d_in[7];
    const float* g1 = (const float*)d_in[8];
    const float* be1= (const float*)d_in[9];
    const float* W2 = (const float*)d_in[10];
    const float* b2 = (const float*)d_in[11];
    const int* row  = (const int*)d_in[12];
    const int* col  = (const int*)d_in[13];
    float* out = (float*)d_out;

    float *pA; __half *pH;
    cudaGetSymbolAddress((void**)&pA, g_bufA);
    cudaGetSymbolAddress((void**)&pH, g_h16);

    static cudaStream_t s_csr = nullptr;
    static cudaEvent_t e_fork = nullptr, e_join = nullptr;
    if (s_csr == nullptr) {
        cudaStreamCreateWithFlags(&s_csr, cudaStreamNonBlocking);
        cudaEventCreateWithFlags(&e_fork, cudaEventDisableTiming);
        cudaEventCreateWithFlags(&e_join, cudaEventDisableTiming);
        cudaFuncSetAttribute(k_gemm_tc, cudaFuncAttributeMaxDynamicSharedMemorySize, GEMM_SMEM);
    }

    int gb256_N = (NN + 255) / 256;
    int gb256_E = (EE + 255) / 256;
    int gemm_blocks = (NN + 127) / 128;
    int spmm_blocks = 1184;

    // fork: CSR build + stats zero run concurrently with W prep + layer-0 GEMM
    cudaEventRecord(e_fork, 0);
    cudaStreamWaitEvent(s_csr, e_fork, 0);
    k_zero_cnt<<<gb256_N, 256, 0, s_csr>>>();
    k_count<<<gb256_E, 256, 0, s_csr>>>(row);
    k_scan1<<<NB_SCAN, 1024, 0, s_csr>>>();
    k_scan2<<<1, 128, 0, s_csr>>>(NB_SCAN);
    k_scan3<<<gb256_N, 256, 0, s_csr>>>();
    k_fill<<<gb256_E, 256, 0, s_csr>>>(row, col, ew);
    cudaEventRecord(e_join, s_csr);

    // main stream: layer 0 GEMM
    k_wprep<<<3 * 128, 128>>>(W0, W1, W2);
    k_gemm_tc<<<gemm_blocks, 256, GEMM_SMEM>>>(x, 0, b0, 0, pH, NN);

    // join CSR before SpMM
    cudaStreamWaitEvent(0, e_join, 0);

    k_spmm3<<<spmm_blocks, 256>>>((const uint4*)pH, (float4*)pA, 0);
    k_bnparams<<<1, 128>>>(g0, be0, 0);

    // layer 1
    k_gemm_tc<<<gemm_blocks, 256, GEMM_SMEM>>>(pA, 1, b1, 1, pH, NN);
    k_spmm3<<<spmm_blocks, 256>>>((const uint4*)pH, (float4*)pA, 1);
    k_bnparams<<<1, 128>>>(g1, be1, 1);

    // layer 2 (no stats)
    k_gemm_tc<<<gemm_blocks, 256, GEMM_SMEM>>>(pA, 2, b2, 1, pH, NN);
    k_spmm3<<<spmm_blocks, 256>>>((const uint4*)pH, (float4*)out, -1);
}

// round 5
// speedup vs baseline: 2.0635x; 1.1306x over previous
#include <cuda_runtime.h>
#include <cuda_fp16.h>
#include <math.h>
#include <stdint.h>

#define NN 100000
#define DD 128
#define EE 1600000
#define NB_SCAN 98
#define BN_EPS 1e-5f

// ---------------- helpers ----------------
__device__ __forceinline__ uint32_t smem_u32(const void* p) {
    uint32_t a;
    asm("{ .reg .u64 t; cvta.to.shared.u64 t, %1; cvt.u32.u64 %0, t; }" : "=r"(a) : "l"(p));
    return a;
}
__device__ __forceinline__ void ldsm4(uint32_t* r, uint32_t a) {
    asm volatile("ldmatrix.sync.aligned.m8n8.x4.shared.b16 {%0,%1,%2,%3}, [%4];"
        : "=r"(r[0]), "=r"(r[1]), "=r"(r[2]), "=r"(r[3]) : "r"(a));
}
__device__ __forceinline__ void ldsm4t(uint32_t* r, uint32_t a) {
    asm volatile("ldmatrix.sync.aligned.m8n8.x4.trans.shared.b16 {%0,%1,%2,%3}, [%4];"
        : "=r"(r[0]), "=r"(r[1]), "=r"(r[2]), "=r"(r[3]) : "r"(a));
}
__device__ __forceinline__ void mma_f16(float* c, const uint32_t* a, uint32_t b0, uint32_t b1) {
    asm volatile("mma.sync.aligned.m16n8k16.row.col.f32.f16.f16.f32 "
        "{%0,%1,%2,%3}, {%4,%5,%6,%7}, {%8,%9}, {%0,%1,%2,%3};"
        : "+f"(c[0]), "+f"(c[1]), "+f"(c[2]), "+f"(c[3])
        : "r"(a[0]), "r"(a[1]), "r"(a[2]), "r"(a[3]), "r"(b0), "r"(b1));
}

// ---------------- device scratch ----------------
__device__ float  g_bufA[NN * DD];                 // fp32 spmm output / gemm input
__device__ __align__(16) __half g_h16[NN * DD];    // fp16 gemm output / spmm gather source
__device__ int   g_cnt[NN];
__device__ int   g_rptr[NN + 1];
__device__ int   g_part[128];
__device__ int   g_part2[128];
__device__ int   g_cols[EE];
__device__ float g_wval[EE];
__device__ float g_sum[2][DD];
__device__ float g_sq[2][DD];
__device__ float g_scale[DD];
__device__ float g_shift[DD];
// W images: [layer][hi/lo][k:128][n:136 padded] fp16
__device__ __align__(16) __half g_wimg[3][2][128][136];

// ---------------- CSR build ----------------
__global__ void k_zero_cnt() {
    int i = blockIdx.x * blockDim.x + threadIdx.x;
    if (i < NN) g_cnt[i] = 0;
    if (i < 2 * DD) { (&g_sum[0][0])[i] = 0.f; (&g_sq[0][0])[i] = 0.f; }
}
__global__ void k_count(const int* __restrict__ row) {
    int e = blockIdx.x * blockDim.x + threadIdx.x;
    if (e < EE) atomicAdd(&g_cnt[row[e]], 1);
}
__global__ __launch_bounds__(1024) void k_scan1() {
    __shared__ int s[1024];
    int t = threadIdx.x;
    int i = blockIdx.x * 1024 + t;
    int v = (i < NN) ? g_cnt[i] : 0;
    s[t] = v;
    #pragma unroll
    for (int off = 1; off < 1024; off <<= 1) {
        __syncthreads();
        int x = (t >= off) ? s[t - off] : 0;
        __syncthreads();
        s[t] += x;
    }
    int incl = s[t];
    if (i < NN) g_rptr[i] = incl - v;
    if (t == 1023) g_part[blockIdx.x] = incl;
}
__global__ void k_scan2(int nb) {
    __shared__ int s[128];
    int t = threadIdx.x;
    int v = (t < nb) ? g_part[t] : 0;
    s[t] = v;
    #pragma unroll
    for (int off = 1; off < 128; off <<= 1) {
        __syncthreads();
        int x = (t >= off) ? s[t - off] : 0;
        __syncthreads();
        s[t] += x;
    }
    g_part2[t] = s[t] - v;
}
__global__ void k_scan3() {
    int i = blockIdx.x * blockDim.x + threadIdx.x;
    if (i < NN) {
        int v = g_rptr[i] + g_part2[i >> 10];
        g_rptr[i] = v;
        g_cnt[i] = v;
    }
    if (i == 0) g_rptr[NN] = EE;
}
__global__ void k_fill(const int* __restrict__ row, const int* __restrict__ col,
                       const float* __restrict__ ew) {
    int e = blockIdx.x * blockDim.x + threadIdx.x;
    if (e < EE) {
        int r = row[e];
        int p = atomicAdd(&g_cnt[r], 1);
        g_cols[p] = col[e];
        g_wval[p] = ew[e];
    }
}

// ---------------- W prep: fp16 hi/lo split, [k][n] layout ----------------
__global__ void k_wprep(const float* __restrict__ W0, const float* __restrict__ W1,
                        const float* __restrict__ W2) {
    int l = blockIdx.x / 128;
    int k = blockIdx.x % 128;
    int n = threadIdx.x;
    const float* W = (l == 0) ? W0 : (l == 1) ? W1 : W2;
    float w = W[k * 128 + n];
    __half hi = __float2half_rn(w);
    __half lo = __float2half_rn(w - __half2float(hi));
    g_wimg[l][0][k][n] = hi;
    g_wimg[l][1][k][n] = lo;
}

// ---------------- tensor-core GEMM via mma.sync fp16x3, fp16 output ----------------
#define GEMM_SMEM (18432 * 2 + 17408 * 2)

__global__ __launch_bounds__(256) void k_gemm_tc(
    const float* __restrict__ A, int layer,
    const float* __restrict__ bias, int useBN,
    __half* __restrict__ out16, int M)
{
    extern __shared__ char sm[];
    __half* sAh = (__half*)sm;              // [128][72]
    __half* sAl = (__half*)(sm + 18432);
    int t = threadIdx.x, lane = t & 31, wid = t >> 5;
    int m0 = blockIdx.x * 128;
    int m_warp = (wid & 1) * 64;
    int n_warp = (wid >> 1) * 32;

    uint32_t sbase = smem_u32(sm);
    uint32_t aAddrH = sbase + (uint32_t)(((m_warp + (lane & 15)) * 72 + (lane >> 4) * 8) * 2);
    uint32_t aAddrL = aAddrH + 18432;
    uint32_t wAddrH = sbase + 36864u + (uint32_t)(((lane & 15) * 136 + n_warp + (lane >> 4) * 8) * 2);
    uint32_t wAddrL = wAddrH + 17408;

    float acc[4][4][4] = {};

    for (int ch = 0; ch < 2; ch++) {
        const float4* whi = (const float4*)&g_wimg[layer][0][ch * 64][0];
        const float4* wlo = (const float4*)&g_wimg[layer][1][ch * 64][0];
        float4* dWh = (float4*)(sm + 36864);
        float4* dWl = (float4*)(sm + 54272);
        #pragma unroll
        for (int i = 0; i < 5; i++) {
            int idx = t + i * 256;
            if (idx < 1088) { dWh[idx] = whi[idx]; dWl[idx] = wlo[idx]; }
        }
        #pragma unroll
        for (int i = 0; i < 8; i++) {
            int idx = t + i * 256;
            int r = idx >> 4, kq = idx & 15;
            int gr = m0 + r;
            float4 v = make_float4(0.f, 0.f, 0.f, 0.f);
            if (gr < M) v = *(const float4*)(A + gr * 128 + ch * 64 + kq * 4);
            if (useBN) {
                int kg = ch * 64 + kq * 4;
                v.x = fmaxf(0.f, fmaf(v.x, g_scale[kg + 0], g_shift[kg + 0]));
                v.y = fmaxf(0.f, fmaf(v.y, g_scale[kg + 1], g_shift[kg + 1]));
                v.z = fmaxf(0.f, fmaf(v.z, g_scale[kg + 2], g_shift[kg + 2]));
                v.w = fmaxf(0.f, fmaf(v.w, g_scale[kg + 3], g_shift[kg + 3]));
            }
            __half hx = __float2half_rn(v.x), hy = __float2half_rn(v.y);
            __half hz = __float2half_rn(v.z), hw = __float2half_rn(v.w);
            __half2 h01 = __halves2half2(hx, hy), h23 = __halves2half2(hz, hw);
            __half2 l01 = __floats2half2_rn(v.x - __half2float(hx), v.y - __half2float(hy));
            __half2 l23 = __floats2half2_rn(v.z - __half2float(hz), v.w - __half2float(hw));
            uint2 uh, ul;
            uh.x = *(uint32_t*)&h01; uh.y = *(uint32_t*)&h23;
            ul.x = *(uint32_t*)&l01; ul.y = *(uint32_t*)&l23;
            *(uint2*)&sAh[r * 72 + kq * 4] = uh;
            *(uint2*)&sAl[r * 72 + kq * 4] = ul;
        }
        __syncthreads();

        #pragma unroll
        for (int ks = 0; ks < 4; ks++) {
            int k0 = ks * 16;
            uint32_t Ah[4][4], Al[4][4], Wh[2][4], Wl[2][4];
            #pragma unroll
            for (int mt = 0; mt < 4; mt++) {
                uint32_t off = (uint32_t)((mt * 16 * 72 + k0) * 2);
                ldsm4(Ah[mt], aAddrH + off);
                ldsm4(Al[mt], aAddrL + off);
            }
            #pragma unroll
            for (int ng = 0; ng < 2; ng++) {
                uint32_t off = (uint32_t)((k0 * 136 + ng * 16) * 2);
                ldsm4t(Wh[ng], wAddrH + off);
                ldsm4t(Wl[ng], wAddrL + off);
            }
            #pragma unroll
            for (int mt = 0; mt < 4; mt++)
                #pragma unroll
                for (int nt = 0; nt < 4; nt++) {
                    int ng = nt >> 1, s = (nt & 1) * 2;
                    mma_f16(acc[mt][nt], Ah[mt], Wh[ng][s], Wh[ng][s + 1]);
                    mma_f16(acc[mt][nt], Ah[mt], Wl[ng][s], Wl[ng][s + 1]);
                    mma_f16(acc[mt][nt], Al[mt], Wh[ng][s], Wh[ng][s + 1]);
                }
        }
        __syncthreads();
    }

    // epilogue + bias, fp16 store
    #pragma unroll
    for (int mt = 0; mt < 4; mt++) {
        int r0 = m0 + m_warp + mt * 16 + (lane >> 2);
        #pragma unroll
        for (int nt = 0; nt < 4; nt++) {
            int col = n_warp + nt * 8 + (lane & 3) * 2;
            float b0 = bias[col], b1 = bias[col + 1];
            if (r0 < M) {
                __half2 o = __floats2half2_rn(acc[mt][nt][0] + b0, acc[mt][nt][1] + b1);
                *(__half2*)(out16 + r0 * 128 + col) = o;
            }
            if (r0 + 8 < M) {
                __half2 o = __floats2half2_rn(acc[mt][nt][2] + b0, acc[mt][nt][3] + b1);
                *(__half2*)(out16 + (r0 + 8) * 128 + col) = o;
            }
        }
    }
}

// ---------------- SpMM gather (fp16 rows) + fused BN stats, MLP=4 per half-warp ----------------
__global__ __launch_bounds__(256) void k_spmm3(const uint4* __restrict__ h16,
                                               float4* __restrict__ out4, int statSlot)
{
    __shared__ float ssum[DD];
    __shared__ float ssq[DD];
    int t = threadIdx.x;
    if (statSlot >= 0) {
        if (t < DD) { ssum[t] = 0.f; ssq[t] = 0.f; }
        __syncthreads();
    }
    int lane = t & 31;
    int hw = lane >> 4;       // half-warp id
    int sl = lane & 15;       // slot: covers cols 8*sl..8*sl+7
    int gw = (blockIdx.x * 256 + t) >> 5;
    int nw = (gridDim.x * 256) >> 5;

    float as[8] = {}, aq[8] = {};

    for (int r = gw; r < NN; r += nw) {
        int jb = g_rptr[r], je = g_rptr[r + 1];
        float acc[8] = {};
        for (int j0 = jb; j0 < je; j0 += 32) {
            int myj = j0 + lane;
            int c = 0; float w = 0.f;
            if (myj < je) { c = g_cols[myj]; w = g_wval[myj]; }
            int cnt = min(32, je - j0);
            // groups of 8 edges: 4 per half-warp, 4 independent gathers in flight
            for (int i = 0; i < cnt; i += 8) {
                int cc[4]; float ww[4]; uint4 hv[4];
                #pragma unroll
                for (int u = 0; u < 4; u++) {
                    int idx = i + u * 2 + hw;
                    int c_s   = __shfl_sync(0xffffffffu, c, idx & 31);
                    float w_s = __shfl_sync(0xffffffffu, w, idx & 31);
                    bool ok = (idx < cnt);
                    cc[u] = ok ? c_s : 0;
                    ww[u] = ok ? w_s : 0.f;
                }
                #pragma unroll
                for (int u = 0; u < 4; u++)
                    hv[u] = h16[cc[u] * 16 + sl];
                #pragma unroll
                for (int u = 0; u < 4; u++) {
                    float2 f0 = __half22float2(*(__half2*)&hv[u].x);
                    float2 f1 = __half22float2(*(__half2*)&hv[u].y);
                    float2 f2 = __half22float2(*(__half2*)&hv[u].z);
                    float2 f3 = __half22float2(*(__half2*)&hv[u].w);
                    acc[0] = fmaf(ww[u], f0.x, acc[0]);
                    acc[1] = fmaf(ww[u], f0.y, acc[1]);
                    acc[2] = fmaf(ww[u], f1.x, acc[2]);
                    acc[3] = fmaf(ww[u], f1.y, acc[3]);
                    acc[4] = fmaf(ww[u], f2.x, acc[4]);
                    acc[5] = fmaf(ww[u], f2.y, acc[5]);
                    acc[6] = fmaf(ww[u], f3.x, acc[6]);
                    acc[7] = fmaf(ww[u], f3.y, acc[7]);
                }
            }
        }
        // combine half-warps
        #pragma unroll
        for (int k = 0; k < 8; k++)
            acc[k] += __shfl_xor_sync(0xffffffffu, acc[k], 16);
        if (lane < 16) {
            float4 o0 = make_float4(acc[0], acc[1], acc[2], acc[3]);
            float4 o1 = make_float4(acc[4], acc[5], acc[6], acc[7]);
            out4[r * 32 + sl * 2 + 0] = o0;
            out4[r * 32 + sl * 2 + 1] = o1;
            if (statSlot >= 0) {
                #pragma unroll
                for (int k = 0; k < 8; k++) {
                    as[k] += acc[k];
                    aq[k] = fmaf(acc[k], acc[k], aq[k]);
                }
            }
        }
    }
    if (statSlot >= 0) {
        if (lane < 16) {
            #pragma unroll
            for (int k = 0; k < 8; k++) {
                atomicAdd(&ssum[sl * 8 + k], as[k]);
                atomicAdd(&ssq[sl * 8 + k], aq[k]);
            }
        }
        __syncthreads();
        if (t < DD) {
            atomicAdd(&g_sum[statSlot][t], ssum[t]);
            atomicAdd(&g_sq[statSlot][t], ssq[t]);
        }
    }
}

// ---------------- BN params ----------------
__global__ void k_bnparams(const float* __restrict__ gamma, const float* __restrict__ beta,
                           int slot) {
    int t = threadIdx.x;
    if (t >= DD) return;
    float invn = 1.0f / (float)NN;
    float m = g_sum[slot][t] * invn;
    float v = g_sq[slot][t] * invn - m * m;
    float sc = gamma[t] * rsqrtf(v + BN_EPS);
    g_scale[t] = sc;
    g_shift[t] = beta[t] - sc * m;
}

// ---------------- launch ----------------
extern "C" void kernel_launch(void* const* d_in, const int* in_sizes, int n_in,
                              void* d_out, int out_size) {
    (void)in_sizes; (void)n_in; (void)out_size;
    const float* x  = (const float*)d_in[0];
    const float* ew = (const float*)d_in[1];
    const float* W0 = (const float*)d_in[2];
    const float* b0 = (const float*)d_in[3];
    const float* g0 = (const float*)d_in[4];
    const float* be0= (const float*)d_in[5];
    const float* W1 = (const float*)d_in[6];
    const float* b1 = (const float*)d_in[7];
    const float* g1 = (const float*)d_in[8];
    const float* be1= (const float*)d_in[9];
    const float* W2 = (const float*)d_in[10];
    const float* b2 = (const float*)d_in[11];
    const int* row  = (const int*)d_in[12];
    const int* col  = (const int*)d_in[13];
    float* out = (float*)d_out;

    float *pA; __half *pH;
    cudaGetSymbolAddress((void**)&pA, g_bufA);
    cudaGetSymbolAddress((void**)&pH, g_h16);

    static cudaStream_t s_csr = nullptr;
    static cudaEvent_t e_fork = nullptr, e_join = nullptr;
    if (s_csr == nullptr) {
        cudaStreamCreateWithFlags(&s_csr, cudaStreamNonBlocking);
        cudaEventCreateWithFlags(&e_fork, cudaEventDisableTiming);
        cudaEventCreateWithFlags(&e_join, cudaEventDisableTiming);
        cudaFuncSetAttribute(k_gemm_tc, cudaFuncAttributeMaxDynamicSharedMemorySize, GEMM_SMEM);
    }

    int gb256_N = (NN + 255) / 256;
    int gb256_E = (EE + 255) / 256;
    int gemm_blocks = (NN + 127) / 128;
    int spmm_blocks = 1184;

    // fork: CSR build + stats zero run concurrently with W prep + layer-0 GEMM
    cudaEventRecord(e_fork, 0);
    cudaStreamWaitEvent(s_csr, e_fork, 0);
    k_zero_cnt<<<gb256_N, 256, 0, s_csr>>>();
    k_count<<<gb256_E, 256, 0, s_csr>>>(row);
    k_scan1<<<NB_SCAN, 1024, 0, s_csr>>>();
    k_scan2<<<1, 128, 0, s_csr>>>(NB_SCAN);
    k_scan3<<<gb256_N, 256, 0, s_csr>>>();
    k_fill<<<gb256_E, 256, 0, s_csr>>>(row, col, ew);
    cudaEventRecord(e_join, s_csr);

    // main stream: layer 0 GEMM
    k_wprep<<<3 * 128, 128>>>(W0, W1, W2);
    k_gemm_tc<<<gemm_blocks, 256, GEMM_SMEM>>>(x, 0, b0, 0, pH, NN);

    // join CSR before SpMM
    cudaStreamWaitEvent(0, e_join, 0);

    k_spmm3<<<spmm_blocks, 256>>>((const uint4*)pH, (float4*)pA, 0);
    k_bnparams<<<1, 128>>>(g0, be0, 0);

    // layer 1
    k_gemm_tc<<<gemm_blocks, 256, GEMM_SMEM>>>(pA, 1, b1, 1, pH, NN);
    k_spmm3<<<spmm_blocks, 256>>>((const uint4*)pH, (float4*)pA, 1);
    k_bnparams<<<1, 128>>>(g1, be1, 1);

    // layer 2 (no stats)
    k_gemm_tc<<<gemm_blocks, 256, GEMM_SMEM>>>(pA, 2, b2, 1, pH, NN);
    k_spmm3<<<spmm_blocks, 256>>>((const uint4*)pH, (float4*)out, -1);
}